// round 15
// baseline (speedup 1.0000x reference)
#include <cuda_runtime.h>
#include <cuda_fp16.h>
#include <math.h>
#include <stdint.h>

#define BATCH 4096
#define HID   1024
#define NOUT  4096   // 4*H

// Scratch (graph-capture safe static device globals)
__device__ __half g_ifgo[(size_t)BATCH * NOUT];  // fp16 pre-activations
__device__ __half g_hh [(size_t)BATCH * HID];    // fp16(RNE) h
__device__ __half g_xh [(size_t)BATCH * HID];    // fp16(RNE) x
__device__ __half g_Whp[(size_t)HID * NOUT];     // packed [k/8][n][8] fp16
__device__ __half g_Wxp[(size_t)HID * NOUT];

// ---------------------------------------------------------------------------
// Merged prepass: blocks [0,1024) convert h/x -> fp16; blocks [1024,5120)
// pack W_h / W_x -> [k/8][n][8] fp16 RNE.
// ---------------------------------------------------------------------------
#define CVT_BLOCKS 1024
#define PACK_BLOCKS_PER_W 2048     // (NOUT/256) * (HID/8)

__global__ __launch_bounds__(256) void prepass_kernel(
    const float* __restrict__ h, const float* __restrict__ x,
    const float* __restrict__ W_h, const float* __restrict__ W_x)
{
    const int blk = blockIdx.x;
    const int tid = threadIdx.x;
    if (blk < CVT_BLOCKS) {
        const int n4 = BATCH * HID / 4;
        const float4* s0 = (const float4*)h;
        const float4* s1 = (const float4*)x;
        __half2* d0 = (__half2*)g_hh;
        __half2* d1 = (__half2*)g_xh;
        int stride = CVT_BLOCKS * 256;
        for (int i = blk * 256 + tid; i < n4; i += stride) {
            float4 v0 = s0[i];
            d0[2 * i + 0] = __floats2half2_rn(v0.x, v0.y);
            d0[2 * i + 1] = __floats2half2_rn(v0.z, v0.w);
            float4 v1 = s1[i];
            d1[2 * i + 0] = __floats2half2_rn(v1.x, v1.y);
            d1[2 * i + 1] = __floats2half2_rn(v1.z, v1.w);
        }
    } else {
        int pb = blk - CVT_BLOCKS;
        const float* W  = (pb < PACK_BLOCKS_PER_W) ? W_h : W_x;
        __half*      Wp = (pb < PACK_BLOCKS_PER_W) ? g_Whp : g_Wxp;
        if (pb >= PACK_BLOCKS_PER_W) pb -= PACK_BLOCKS_PER_W;
        const int n  = (pb & 15) * 256 + tid;    // 16 n-blocks
        const int ko = pb >> 4;                  // 0..127
        __half tmp[8];
        #pragma unroll
        for (int j = 0; j < 8; ++j)
            tmp[j] = __float2half_rn(W[(size_t)(ko * 8 + j) * NOUT + n]);
        *(uint4*)&Wp[((size_t)ko * NOUT + n) * 8] = *(uint4*)tmp;
    }
}

// ---------------------------------------------------------------------------
// fp16 mma.sync GEMM: ifgo = h @ W_h + x @ W_x + b_h   (fp32 accumulate)
// CTA 128x128, 8 warps (4x2 of 32x64), BK=32, 5-stage cp.async ring,
// m16n8k16, cross-tile X/Y fragment ping-pong at k16 granularity.
// ---------------------------------------------------------------------------
#define BM 128
#define BN 128
#define BK 32
#define AROW_B 80                   // A smem row stride bytes (64 data + 16 pad)
#define STAGES 5
#define NKTILES 64                  // 2 passes * (1024/32)
#define A_STG_B (BM * AROW_B)       // 10240 B
#define B_STG_B (BK * BN * 2)       //  8192 B
#define GEMM_SMEM ((A_STG_B + B_STG_B) * STAGES)   // 92160 B

__device__ __forceinline__ void cpa16(uint32_t dst, const void* src) {
    asm volatile("cp.async.cg.shared.global [%0], [%1], 16;\n" :: "r"(dst), "l"(src));
}
__device__ __forceinline__ void cpa_commit() {
    asm volatile("cp.async.commit_group;\n" ::: "memory");
}
__device__ __forceinline__ void cpa_wait3() {
    asm volatile("cp.async.wait_group 3;\n" ::: "memory");
}
__device__ __forceinline__ void ldsm_x4(uint32_t* r, uint32_t addr) {
    asm volatile("ldmatrix.sync.aligned.m8n8.x4.shared.b16 {%0,%1,%2,%3}, [%4];"
                 : "=r"(r[0]), "=r"(r[1]), "=r"(r[2]), "=r"(r[3]) : "r"(addr));
}

__global__ __launch_bounds__(256, 2) void gemm_fp16_kernel(const float* __restrict__ b_h)
{
    extern __shared__ char smem[];
    char* As = smem;                               // STAGES x A_STG_B
    char* Bs = smem + STAGES * A_STG_B;            // STAGES x B_STG_B

    const int tid  = threadIdx.x;
    const int lane = tid & 31;
    const int wid  = tid >> 5;         // 0..7
    const int wm   = wid >> 1;         // 0..3 -> 32 rows
    const int wn   = wid & 1;          // 0..1 -> 64 cols
    const int qid  = lane >> 2;        // 0..7
    const int cid  = lane & 3;         // 0..3
    const int mi   = lane >> 3;        // ldmatrix matrix index 0..3

    const int brow = blockIdx.y * BM;
    const int bcol = blockIdx.x * BN;

    const __half* Aops[2] = { g_hh, g_xh };
    const __half* Wops[2] = { g_Whp, g_Wxp };

    const uint32_t as_u = (uint32_t)__cvta_generic_to_shared(As);
    const uint32_t bs_u = (uint32_t)__cvta_generic_to_shared(Bs);

    const int a_lane_by = ((mi & 1) * 8 + (lane & 7)) * AROW_B + (mi >> 1) * 16;
    const int b_lane_by = (mi & 1) * 2048 + (wn * 64 + (mi >> 1) * 8 + (lane & 7)) * 16;

    const uint32_t a_warp_u = as_u + (uint32_t)(wm * 32 * AROW_B + a_lane_by);
    const uint32_t b_warp_u = bs_u + (uint32_t)b_lane_by;

    auto stage = [&](int t, int buf) {
        const int pass = t >> 5;
        const int kloc = t & 31;
        const __half* A = Aops[pass];
        const __half* W = Wops[pass];
        const __half* asrc = A + (size_t)(brow + (tid >> 1)) * HID + kloc * 32 + (tid & 1) * 16;
        uint32_t adst = as_u + (uint32_t)(buf * A_STG_B + (tid >> 1) * AROW_B + (tid & 1) * 32);
        cpa16(adst,       asrc);
        cpa16(adst + 16u, asrc + 8);
        #pragma unroll
        for (int cch = 0; cch < 2; ++cch) {
            int cidx = tid * 2 + cch;
            int q = cidx >> 7, n = cidx & 127;
            const __half* bsrc = W + ((size_t)(kloc * 4 + q) * NOUT + bcol + n) * 8;
            uint32_t bdst = bs_u + (uint32_t)(buf * B_STG_B + q * 2048 + n * 16);
            cpa16(bdst, bsrc);
        }
        cpa_commit();
    };

    auto load_frags = [&](int buf, int g, uint32_t (&af)[2][4], uint32_t (&bf)[4][4]) {
        const uint32_t a_base = a_warp_u + (uint32_t)(buf * A_STG_B + g * 32);
        const uint32_t b_base = b_warp_u + (uint32_t)(buf * B_STG_B + g * 4096);
        #pragma unroll
        for (int i = 0; i < 2; ++i)
            ldsm_x4(af[i], a_base + (uint32_t)(i * 16 * AROW_B));
        #pragma unroll
        for (int p = 0; p < 4; ++p)
            ldsm_x4(bf[p], b_base + (uint32_t)(p * 256));
    };

    float acc[2][8][4];
    #pragma unroll
    for (int i = 0; i < 2; ++i)
        #pragma unroll
        for (int j = 0; j < 8; ++j)
            #pragma unroll
            for (int r = 0; r < 4; ++r) acc[i][j][r] = 0.f;

    auto mma_half = [&](uint32_t (&af)[2][4], uint32_t (&bf)[4][4]) {
        #pragma unroll
        for (int j = 0; j < 8; ++j) {
            uint32_t b0 = bf[j >> 1][(j & 1) * 2 + 0];
            uint32_t b1 = bf[j >> 1][(j & 1) * 2 + 1];
            #pragma unroll
            for (int i = 0; i < 2; ++i) {
                asm volatile(
                    "mma.sync.aligned.m16n8k16.row.col.f32.f16.f16.f32 "
                    "{%0,%1,%2,%3}, {%4,%5,%6,%7}, {%8,%9}, {%0,%1,%2,%3};\n"
                    : "+f"(acc[i][j][0]), "+f"(acc[i][j][1]),
                      "+f"(acc[i][j][2]), "+f"(acc[i][j][3])
                    : "r"(af[i][0]), "r"(af[i][1]), "r"(af[i][2]), "r"(af[i][3]),
                      "r"(b0), "r"(b1));
            }
        }
    };

    stage(0, 0); stage(1, 1); stage(2, 2); stage(3, 3);
    cpa_wait3();
    __syncthreads();

    uint32_t afX[2][4], bfX[4][4];
    uint32_t afY[2][4], bfY[4][4];

    load_frags(0, 0, afX, bfX);

    int buf = 0, sbuf = 4;
    #pragma unroll 1
    for (int t = 0; t < NKTILES; ++t) {
        load_frags(buf, 1, afY, bfY);
        mma_half(afX, bfX);

        if (t + 4 < NKTILES) stage(t + 4, sbuf);
        if (++sbuf == STAGES) sbuf = 0;

        if (t + 1 < NKTILES) {
            cpa_wait3();
            __syncthreads();
            int nbuf = (buf + 1 == STAGES) ? 0 : buf + 1;
            load_frags(nbuf, 0, afX, bfX);
            buf = nbuf;
        }

        mma_half(afY, bfY);
    }

    // Epilogue: bias + convert to fp16 + store
    #pragma unroll
    for (int i = 0; i < 2; ++i) {
        int r0 = brow + wm * 32 + i * 16 + qid;
        #pragma unroll
        for (int j = 0; j < 8; ++j) {
            int col = bcol + wn * 64 + j * 8 + 2 * cid;
            float2 bb = *(const float2*)&b_h[col];
            __half2 v0 = __floats2half2_rn(acc[i][j][0] + bb.x, acc[i][j][1] + bb.y);
            __half2 v1 = __floats2half2_rn(acc[i][j][2] + bb.x, acc[i][j][3] + bb.y);
            *(__half2*)&g_ifgo[(size_t)r0       * NOUT + col] = v0;
            *(__half2*)&g_ifgo[(size_t)(r0 + 8) * NOUT + col] = v1;
        }
    }
}

// ---------------------------------------------------------------------------
// Kernel 2: per-row LayerNorm(4 gates) + LSTM pointwise + LayerNorm(c_next)
// 1 row per block (grid 4096); fp16 ifgo input; tanh.approx; 6 blocks/SM.
// ---------------------------------------------------------------------------
__device__ __forceinline__ float tanh_ap(float v) {
    float r;
    asm("tanh.approx.f32 %0, %1;" : "=f"(r) : "f"(v));
    return r;
}
__device__ __forceinline__ float sigmoid_ap(float v) {
    return fmaf(tanh_ap(0.5f * v), 0.5f, 0.5f);
}
__device__ __forceinline__ float4 ld_h4(const __half* p) {
    uint2 u = *(const uint2*)p;
    float2 a = __half22float2(*(__half2*)&u.x);
    float2 b = __half22float2(*(__half2*)&u.y);
    return make_float4(a.x, a.y, b.x, b.y);
}

__global__ __launch_bounds__(256, 6) void ln_lstm_kernel(
    const float* __restrict__ c,
    const float* __restrict__ ln_g, const float* __restrict__ ln_b,
    const float* __restrict__ lnc_g, const float* __restrict__ lnc_b,
    float* __restrict__ h_next, float* __restrict__ c_next_out)
{
    const int b    = blockIdx.x;
    const int tid  = threadIdx.x;
    const int lane = tid & 31, warp = tid >> 5;
    const __half* __restrict__ row = &g_ifgo[(size_t)b * NOUT];
    const int j4 = tid * 4;

    __shared__ float s_st[8][8];
    __shared__ float s_stats[8];
    __shared__ float s_c2[8][2];
    __shared__ float s_cstat[2];

    float4 vi = ld_h4(&row[0 * HID + j4]);
    float4 vf = ld_h4(&row[1 * HID + j4]);
    float4 vg = ld_h4(&row[2 * HID + j4]);
    float4 vo = ld_h4(&row[3 * HID + j4]);

    float st[8];
    st[0] = vi.x + vi.y + vi.z + vi.w;
    st[1] = vf.x + vf.y + vf.z + vf.w;
    st[2] = vg.x + vg.y + vg.z + vg.w;
    st[3] = vo.x + vo.y + vo.z + vo.w;
    st[4] = vi.x*vi.x + vi.y*vi.y + vi.z*vi.z + vi.w*vi.w;
    st[5] = vf.x*vf.x + vf.y*vf.y + vf.z*vf.z + vf.w*vf.w;
    st[6] = vg.x*vg.x + vg.y*vg.y + vg.z*vg.z + vg.w*vg.w;
    st[7] = vo.x*vo.x + vo.y*vo.y + vo.z*vo.z + vo.w*vo.w;
    #pragma unroll
    for (int o = 16; o > 0; o >>= 1)
        #pragma unroll
        for (int s = 0; s < 8; ++s)
            st[s] += __shfl_down_sync(0xffffffffu, st[s], o);
    if (lane == 0)
        #pragma unroll
        for (int s = 0; s < 8; ++s) s_st[warp][s] = st[s];
    __syncthreads();
    if (warp == 0) {
        float v = s_st[lane >> 3][lane & 7] + s_st[(lane >> 3) + 4][lane & 7];
        v += __shfl_down_sync(0xffffffffu, v, 16);
        v += __shfl_down_sync(0xffffffffu, v, 8);
        if (lane < 8) {
            if (lane < 4) s_stats[lane] = v * (1.0f / HID);
            else          s_st[0][lane] = v * (1.0f / HID);
        }
    }
    __syncthreads();
    if (warp == 0 && lane < 4) {
        float mu = s_stats[lane];
        float ex2 = s_st[0][lane + 4];
        s_stats[lane + 4] = rsqrtf(ex2 - mu * mu + 1e-5f);
    }
    __syncthreads();

    const float mu_i = s_stats[0], mu_f = s_stats[1], mu_g = s_stats[2], mu_o = s_stats[3];
    const float rs_i = s_stats[4], rs_f = s_stats[5], rs_g = s_stats[6], rs_o = s_stats[7];

    float4 gi = *(const float4*)&ln_g[0 * HID + j4];
    float4 gf = *(const float4*)&ln_g[1 * HID + j4];
    float4 gg = *(const float4*)&ln_g[2 * HID + j4];
    float4 go = *(const float4*)&ln_g[3 * HID + j4];
    float4 bi = *(const float4*)&ln_b[0 * HID + j4];
    float4 bff = *(const float4*)&ln_b[1 * HID + j4];
    float4 bg = *(const float4*)&ln_b[2 * HID + j4];
    float4 bo = *(const float4*)&ln_b[3 * HID + j4];
    float4 cv = *(const float4*)&c[(size_t)b * HID + j4];

    float cn[4], ov[4];
    float csum = 0.f, csq = 0.f;
    {
        const float* pvi = &vi.x; const float* pvf = &vf.x;
        const float* pvg = &vg.x; const float* pvo = &vo.x;
        const float* pgi = &gi.x; const float* pgf = &gf.x;
        const float* pgg = &gg.x; const float* pgo = &go.x;
        const float* pbi = &bi.x; const float* pbf = &bff.x;
        const float* pbg = &bg.x; const float* pbo = &bo.x;
        const float* pc  = &cv.x;
        #pragma unroll
        for (int e = 0; e < 4; ++e) {
            float ivv = (pvi[e] - mu_i) * rs_i * pgi[e] + pbi[e];
            float fvv = (pvf[e] - mu_f) * rs_f * pgf[e] + pbf[e];
            float gvv = (pvg[e] - mu_g) * rs_g * pgg[e] + pbg[e];
            ov[e]     = (pvo[e] - mu_o) * rs_o * pgo[e] + pbo[e];
            cn[e] = sigmoid_ap(fvv) * pc[e] + sigmoid_ap(ivv) * tanh_ap(gvv);
            csum += cn[e]; csq += cn[e] * cn[e];
        }
    }
    *(float4*)&c_next_out[(size_t)b * HID + j4] = *(float4*)cn;

    #pragma unroll
    for (int o = 16; o > 0; o >>= 1) {
        csum += __shfl_down_sync(0xffffffffu, csum, o);
        csq  += __shfl_down_sync(0xffffffffu, csq,  o);
    }
    if (lane == 0) { s_c2[warp][0] = csum; s_c2[warp][1] = csq; }
    __syncthreads();
    if (warp == 0) {
        float a2 = (lane < 8) ? s_c2[lane][0] : 0.f;
        float b2 = (lane < 8) ? s_c2[lane][1] : 0.f;
        #pragma unroll
        for (int o = 4; o > 0; o >>= 1) {
            a2 += __shfl_down_sync(0xffffffffu, a2, o);
            b2 += __shfl_down_sync(0xffffffffu, b2, o);
        }
        if (lane == 0) {
            float mu  = a2 * (1.0f / HID);
            float var = b2 * (1.0f / HID) - mu * mu;
            s_cstat[0] = mu;
            s_cstat[1] = rsqrtf(var + 1e-5f);
        }
    }
    __syncthreads();

    const float cmu = s_cstat[0], crstd = s_cstat[1];
    float4 lg = *(const float4*)&lnc_g[j4];
    float4 lb = *(const float4*)&lnc_b[j4];
    float hn[4];
    {
        const float* plg = &lg.x; const float* plb = &lb.x;
        #pragma unroll
        for (int e = 0; e < 4; ++e) {
            float lnc = (cn[e] - cmu) * crstd * plg[e] + plb[e];
            hn[e] = sigmoid_ap(ov[e]) * tanh_ap(lnc);
        }
    }
    *(float4*)&h_next[(size_t)b * HID + j4] = *(float4*)hn;
}

// ---------------------------------------------------------------------------
extern "C" void kernel_launch(void* const* d_in, const int* in_sizes, int n_in,
                              void* d_out, int out_size)
{
    const float* x     = (const float*)d_in[0];
    const float* h     = (const float*)d_in[1];
    const float* c     = (const float*)d_in[2];
    const float* W_h   = (const float*)d_in[3];
    const float* b_h   = (const float*)d_in[4];
    const float* W_x   = (const float*)d_in[5];
    const float* ln_g  = (const float*)d_in[6];
    const float* ln_b  = (const float*)d_in[7];
    const float* lnc_g = (const float*)d_in[8];
    const float* lnc_b = (const float*)d_in[9];

    float* out    = (float*)d_out;
    float* h_next = out;
    float* c_next = out + (size_t)BATCH * HID;

    prepass_kernel<<<CVT_BLOCKS + 2 * PACK_BLOCKS_PER_W, 256>>>(h, x, W_h, W_x);

    cudaFuncSetAttribute(gemm_fp16_kernel,
                         cudaFuncAttributeMaxDynamicSharedMemorySize, GEMM_SMEM);
    dim3 grid(NOUT / BN, BATCH / BM);
    gemm_fp16_kernel<<<grid, 256, GEMM_SMEM>>>(b_h);

    ln_lstm_kernel<<<BATCH, 256>>>(c, ln_g, ln_b, lnc_g, lnc_b, h_next, c_next);
}

// round 16
// speedup vs baseline: 1.2929x; 1.2929x over previous
#include <cuda_runtime.h>
#include <cuda_fp16.h>
#include <math.h>
#include <stdint.h>

#define BATCH 4096
#define HID   1024
#define NOUT  4096   // 4*H

// Scratch (graph-capture safe static device globals)
__device__ __half g_ifgo[(size_t)BATCH * NOUT];  // fp16 pre-activations
__device__ __half g_hh [(size_t)BATCH * HID];    // fp16(RNE) h
__device__ __half g_xh [(size_t)BATCH * HID];    // fp16(RNE) x
__device__ __half g_Whp[(size_t)HID * NOUT];     // packed [k/8][n][8] fp16
__device__ __half g_Wxp[(size_t)HID * NOUT];

// ---------------------------------------------------------------------------
// Merged prepass: blocks [0,1024) convert h/x -> fp16; blocks [1024,5120)
// pack W_h / W_x -> [k/8][n][8] fp16 RNE.  (round-15 proven: 16us)
// ---------------------------------------------------------------------------
#define CVT_BLOCKS 1024
#define PACK_BLOCKS_PER_W 2048     // (NOUT/256) * (HID/8)

__global__ __launch_bounds__(256) void prepass_kernel(
    const float* __restrict__ h, const float* __restrict__ x,
    const float* __restrict__ W_h, const float* __restrict__ W_x)
{
    const int blk = blockIdx.x;
    const int tid = threadIdx.x;
    if (blk < CVT_BLOCKS) {
        const int n4 = BATCH * HID / 4;
        const float4* s0 = (const float4*)h;
        const float4* s1 = (const float4*)x;
        __half2* d0 = (__half2*)g_hh;
        __half2* d1 = (__half2*)g_xh;
        int stride = CVT_BLOCKS * 256;
        for (int i = blk * 256 + tid; i < n4; i += stride) {
            float4 v0 = s0[i];
            d0[2 * i + 0] = __floats2half2_rn(v0.x, v0.y);
            d0[2 * i + 1] = __floats2half2_rn(v0.z, v0.w);
            float4 v1 = s1[i];
            d1[2 * i + 0] = __floats2half2_rn(v1.x, v1.y);
            d1[2 * i + 1] = __floats2half2_rn(v1.z, v1.w);
        }
    } else {
        int pb = blk - CVT_BLOCKS;
        const float* W  = (pb < PACK_BLOCKS_PER_W) ? W_h : W_x;
        __half*      Wp = (pb < PACK_BLOCKS_PER_W) ? g_Whp : g_Wxp;
        if (pb >= PACK_BLOCKS_PER_W) pb -= PACK_BLOCKS_PER_W;
        const int n  = (pb & 15) * 256 + tid;    // 16 n-blocks
        const int ko = pb >> 4;                  // 0..127
        __half tmp[8];
        #pragma unroll
        for (int j = 0; j < 8; ++j)
            tmp[j] = __float2half_rn(W[(size_t)(ko * 8 + j) * NOUT + n]);
        *(uint4*)&Wp[((size_t)ko * NOUT + n) * 8] = *(uint4*)tmp;
    }
}

// ---------------------------------------------------------------------------
// fp16 mma.sync GEMM: ifgo = h @ W_h + x @ W_x + b_h   (fp32 accumulate)
// CTA 128x128, 8 warps (4x2 of 32x64), BK=32, 5-stage cp.async ring,
// m16n8k16, cross-tile X/Y fragment ping-pong at k16 granularity.
// ---------------------------------------------------------------------------
#define BM 128
#define BN 128
#define BK 32
#define AROW_B 80                   // A smem row stride bytes (64 data + 16 pad)
#define STAGES 5
#define NKTILES 64                  // 2 passes * (1024/32)
#define A_STG_B (BM * AROW_B)       // 10240 B
#define B_STG_B (BK * BN * 2)       //  8192 B
#define GEMM_SMEM ((A_STG_B + B_STG_B) * STAGES)   // 92160 B

__device__ __forceinline__ void cpa16(uint32_t dst, const void* src) {
    asm volatile("cp.async.cg.shared.global [%0], [%1], 16;\n" :: "r"(dst), "l"(src));
}
__device__ __forceinline__ void cpa_commit() {
    asm volatile("cp.async.commit_group;\n" ::: "memory");
}
__device__ __forceinline__ void cpa_wait3() {
    asm volatile("cp.async.wait_group 3;\n" ::: "memory");
}
__device__ __forceinline__ void ldsm_x4(uint32_t* r, uint32_t addr) {
    asm volatile("ldmatrix.sync.aligned.m8n8.x4.shared.b16 {%0,%1,%2,%3}, [%4];"
                 : "=r"(r[0]), "=r"(r[1]), "=r"(r[2]), "=r"(r[3]) : "r"(addr));
}

__global__ __launch_bounds__(256, 2) void gemm_fp16_kernel(const float* __restrict__ b_h)
{
    extern __shared__ char smem[];
    char* As = smem;                               // STAGES x A_STG_B
    char* Bs = smem + STAGES * A_STG_B;            // STAGES x B_STG_B

    const int tid  = threadIdx.x;
    const int lane = tid & 31;
    const int wid  = tid >> 5;         // 0..7
    const int wm   = wid >> 1;         // 0..3 -> 32 rows
    const int wn   = wid & 1;          // 0..1 -> 64 cols
    const int qid  = lane >> 2;        // 0..7
    const int cid  = lane & 3;         // 0..3
    const int mi   = lane >> 3;        // ldmatrix matrix index 0..3

    const int brow = blockIdx.y * BM;
    const int bcol = blockIdx.x * BN;

    const __half* Aops[2] = { g_hh, g_xh };
    const __half* Wops[2] = { g_Whp, g_Wxp };

    const uint32_t as_u = (uint32_t)__cvta_generic_to_shared(As);
    const uint32_t bs_u = (uint32_t)__cvta_generic_to_shared(Bs);

    const int a_lane_by = ((mi & 1) * 8 + (lane & 7)) * AROW_B + (mi >> 1) * 16;
    const int b_lane_by = (mi & 1) * 2048 + (wn * 64 + (mi >> 1) * 8 + (lane & 7)) * 16;

    const uint32_t a_warp_u = as_u + (uint32_t)(wm * 32 * AROW_B + a_lane_by);
    const uint32_t b_warp_u = bs_u + (uint32_t)b_lane_by;

    auto stage = [&](int t, int buf) {
        const int pass = t >> 5;
        const int kloc = t & 31;
        const __half* A = Aops[pass];
        const __half* W = Wops[pass];
        const __half* asrc = A + (size_t)(brow + (tid >> 1)) * HID + kloc * 32 + (tid & 1) * 16;
        uint32_t adst = as_u + (uint32_t)(buf * A_STG_B + (tid >> 1) * AROW_B + (tid & 1) * 32);
        cpa16(adst,       asrc);
        cpa16(adst + 16u, asrc + 8);
        #pragma unroll
        for (int cch = 0; cch < 2; ++cch) {
            int cidx = tid * 2 + cch;
            int q = cidx >> 7, n = cidx & 127;
            const __half* bsrc = W + ((size_t)(kloc * 4 + q) * NOUT + bcol + n) * 8;
            uint32_t bdst = bs_u + (uint32_t)(buf * B_STG_B + q * 2048 + n * 16);
            cpa16(bdst, bsrc);
        }
        cpa_commit();
    };

    auto load_frags = [&](int buf, int g, uint32_t (&af)[2][4], uint32_t (&bf)[4][4]) {
        const uint32_t a_base = a_warp_u + (uint32_t)(buf * A_STG_B + g * 32);
        const uint32_t b_base = b_warp_u + (uint32_t)(buf * B_STG_B + g * 4096);
        #pragma unroll
        for (int i = 0; i < 2; ++i)
            ldsm_x4(af[i], a_base + (uint32_t)(i * 16 * AROW_B));
        #pragma unroll
        for (int p = 0; p < 4; ++p)
            ldsm_x4(bf[p], b_base + (uint32_t)(p * 256));
    };

    float acc[2][8][4];
    #pragma unroll
    for (int i = 0; i < 2; ++i)
        #pragma unroll
        for (int j = 0; j < 8; ++j)
            #pragma unroll
            for (int r = 0; r < 4; ++r) acc[i][j][r] = 0.f;

    auto mma_half = [&](uint32_t (&af)[2][4], uint32_t (&bf)[4][4]) {
        #pragma unroll
        for (int j = 0; j < 8; ++j) {
            uint32_t b0 = bf[j >> 1][(j & 1) * 2 + 0];
            uint32_t b1 = bf[j >> 1][(j & 1) * 2 + 1];
            #pragma unroll
            for (int i = 0; i < 2; ++i) {
                asm volatile(
                    "mma.sync.aligned.m16n8k16.row.col.f32.f16.f16.f32 "
                    "{%0,%1,%2,%3}, {%4,%5,%6,%7}, {%8,%9}, {%0,%1,%2,%3};\n"
                    : "+f"(acc[i][j][0]), "+f"(acc[i][j][1]),
                      "+f"(acc[i][j][2]), "+f"(acc[i][j][3])
                    : "r"(af[i][0]), "r"(af[i][1]), "r"(af[i][2]), "r"(af[i][3]),
                      "r"(b0), "r"(b1));
            }
        }
    };

    stage(0, 0); stage(1, 1); stage(2, 2); stage(3, 3);
    cpa_wait3();
    __syncthreads();

    uint32_t afX[2][4], bfX[4][4];
    uint32_t afY[2][4], bfY[4][4];

    load_frags(0, 0, afX, bfX);

    int buf = 0, sbuf = 4;
    #pragma unroll 1
    for (int t = 0; t < NKTILES; ++t) {
        load_frags(buf, 1, afY, bfY);
        mma_half(afX, bfX);

        if (t + 4 < NKTILES) stage(t + 4, sbuf);
        if (++sbuf == STAGES) sbuf = 0;

        if (t + 1 < NKTILES) {
            cpa_wait3();
            __syncthreads();
            int nbuf = (buf + 1 == STAGES) ? 0 : buf + 1;
            load_frags(nbuf, 0, afX, bfX);
            buf = nbuf;
        }

        mma_half(afY, bfY);
    }

    // Epilogue: bias + convert to fp16 + store
    #pragma unroll
    for (int i = 0; i < 2; ++i) {
        int r0 = brow + wm * 32 + i * 16 + qid;
        #pragma unroll
        for (int j = 0; j < 8; ++j) {
            int col = bcol + wn * 64 + j * 8 + 2 * cid;
            float2 bb = *(const float2*)&b_h[col];
            __half2 v0 = __floats2half2_rn(acc[i][j][0] + bb.x, acc[i][j][1] + bb.y);
            __half2 v1 = __floats2half2_rn(acc[i][j][2] + bb.x, acc[i][j][3] + bb.y);
            *(__half2*)&g_ifgo[(size_t)r0       * NOUT + col] = v0;
            *(__half2*)&g_ifgo[(size_t)(r0 + 8) * NOUT + col] = v1;
        }
    }
}

// ---------------------------------------------------------------------------
// Kernel 2: per-row LayerNorm(4 gates) + LSTM pointwise + LayerNorm(c_next)
// 1 row per block (grid 4096); fp16 ifgo input; tanh.approx.
// (round-14 proven: regs=53, 25.4us — no min-blocks clamp)
// ---------------------------------------------------------------------------
__device__ __forceinline__ float tanh_ap(float v) {
    float r;
    asm("tanh.approx.f32 %0, %1;" : "=f"(r) : "f"(v));
    return r;
}
__device__ __forceinline__ float sigmoid_ap(float v) {
    return fmaf(tanh_ap(0.5f * v), 0.5f, 0.5f);
}
__device__ __forceinline__ float4 ld_h4(const __half* p) {
    uint2 u = *(const uint2*)p;
    float2 a = __half22float2(*(__half2*)&u.x);
    float2 b = __half22float2(*(__half2*)&u.y);
    return make_float4(a.x, a.y, b.x, b.y);
}

__global__ __launch_bounds__(256) void ln_lstm_kernel(
    const float* __restrict__ c,
    const float* __restrict__ ln_g, const float* __restrict__ ln_b,
    const float* __restrict__ lnc_g, const float* __restrict__ lnc_b,
    float* __restrict__ h_next, float* __restrict__ c_next_out)
{
    const int b    = blockIdx.x;
    const int tid  = threadIdx.x;
    const int lane = tid & 31, warp = tid >> 5;
    const __half* __restrict__ row = &g_ifgo[(size_t)b * NOUT];
    const int j4 = tid * 4;

    __shared__ float s_st[8][8];
    __shared__ float s_stats[8];
    __shared__ float s_c2[8][2];
    __shared__ float s_cstat[2];

    float4 vi = ld_h4(&row[0 * HID + j4]);
    float4 vf = ld_h4(&row[1 * HID + j4]);
    float4 vg = ld_h4(&row[2 * HID + j4]);
    float4 vo = ld_h4(&row[3 * HID + j4]);

    float st[8];
    st[0] = vi.x + vi.y + vi.z + vi.w;
    st[1] = vf.x + vf.y + vf.z + vf.w;
    st[2] = vg.x + vg.y + vg.z + vg.w;
    st[3] = vo.x + vo.y + vo.z + vo.w;
    st[4] = vi.x*vi.x + vi.y*vi.y + vi.z*vi.z + vi.w*vi.w;
    st[5] = vf.x*vf.x + vf.y*vf.y + vf.z*vf.z + vf.w*vf.w;
    st[6] = vg.x*vg.x + vg.y*vg.y + vg.z*vg.z + vg.w*vg.w;
    st[7] = vo.x*vo.x + vo.y*vo.y + vo.z*vo.z + vo.w*vo.w;
    #pragma unroll
    for (int o = 16; o > 0; o >>= 1)
        #pragma unroll
        for (int s = 0; s < 8; ++s)
            st[s] += __shfl_down_sync(0xffffffffu, st[s], o);
    if (lane == 0)
        #pragma unroll
        for (int s = 0; s < 8; ++s) s_st[warp][s] = st[s];
    __syncthreads();
    if (warp == 0) {
        float v = s_st[lane >> 3][lane & 7] + s_st[(lane >> 3) + 4][lane & 7];
        v += __shfl_down_sync(0xffffffffu, v, 16);
        v += __shfl_down_sync(0xffffffffu, v, 8);
        if (lane < 8) {
            if (lane < 4) s_stats[lane] = v * (1.0f / HID);
            else          s_st[0][lane] = v * (1.0f / HID);
        }
    }
    __syncthreads();
    if (warp == 0 && lane < 4) {
        float mu = s_stats[lane];
        float ex2 = s_st[0][lane + 4];
        s_stats[lane + 4] = rsqrtf(ex2 - mu * mu + 1e-5f);
    }
    __syncthreads();

    const float mu_i = s_stats[0], mu_f = s_stats[1], mu_g = s_stats[2], mu_o = s_stats[3];
    const float rs_i = s_stats[4], rs_f = s_stats[5], rs_g = s_stats[6], rs_o = s_stats[7];

    float4 gi = *(const float4*)&ln_g[0 * HID + j4];
    float4 gf = *(const float4*)&ln_g[1 * HID + j4];
    float4 gg = *(const float4*)&ln_g[2 * HID + j4];
    float4 go = *(const float4*)&ln_g[3 * HID + j4];
    float4 bi = *(const float4*)&ln_b[0 * HID + j4];
    float4 bff = *(const float4*)&ln_b[1 * HID + j4];
    float4 bg = *(const float4*)&ln_b[2 * HID + j4];
    float4 bo = *(const float4*)&ln_b[3 * HID + j4];
    float4 cv = *(const float4*)&c[(size_t)b * HID + j4];

    float cn[4], ov[4];
    float csum = 0.f, csq = 0.f;
    {
        const float* pvi = &vi.x; const float* pvf = &vf.x;
        const float* pvg = &vg.x; const float* pvo = &vo.x;
        const float* pgi = &gi.x; const float* pgf = &gf.x;
        const float* pgg = &gg.x; const float* pgo = &go.x;
        const float* pbi = &bi.x; const float* pbf = &bff.x;
        const float* pbg = &bg.x; const float* pbo = &bo.x;
        const float* pc  = &cv.x;
        #pragma unroll
        for (int e = 0; e < 4; ++e) {
            float ivv = (pvi[e] - mu_i) * rs_i * pgi[e] + pbi[e];
            float fvv = (pvf[e] - mu_f) * rs_f * pgf[e] + pbf[e];
            float gvv = (pvg[e] - mu_g) * rs_g * pgg[e] + pbg[e];
            ov[e]     = (pvo[e] - mu_o) * rs_o * pgo[e] + pbo[e];
            cn[e] = sigmoid_ap(fvv) * pc[e] + sigmoid_ap(ivv) * tanh_ap(gvv);
            csum += cn[e]; csq += cn[e] * cn[e];
        }
    }
    *(float4*)&c_next_out[(size_t)b * HID + j4] = *(float4*)cn;

    #pragma unroll
    for (int o = 16; o > 0; o >>= 1) {
        csum += __shfl_down_sync(0xffffffffu, csum, o);
        csq  += __shfl_down_sync(0xffffffffu, csq,  o);
    }
    if (lane == 0) { s_c2[warp][0] = csum; s_c2[warp][1] = csq; }
    __syncthreads();
    if (warp == 0) {
        float a2 = (lane < 8) ? s_c2[lane][0] : 0.f;
        float b2 = (lane < 8) ? s_c2[lane][1] : 0.f;
        #pragma unroll
        for (int o = 4; o > 0; o >>= 1) {
            a2 += __shfl_down_sync(0xffffffffu, a2, o);
            b2 += __shfl_down_sync(0xffffffffu, b2, o);
        }
        if (lane == 0) {
            float mu  = a2 * (1.0f / HID);
            float var = b2 * (1.0f / HID) - mu * mu;
            s_cstat[0] = mu;
            s_cstat[1] = rsqrtf(var + 1e-5f);
        }
    }
    __syncthreads();

    const float cmu = s_cstat[0], crstd = s_cstat[1];
    float4 lg = *(const float4*)&lnc_g[j4];
    float4 lb = *(const float4*)&lnc_b[j4];
    float hn[4];
    {
        const float* plg = &lg.x; const float* plb = &lb.x;
        #pragma unroll
        for (int e = 0; e < 4; ++e) {
            float lnc = (cn[e] - cmu) * crstd * plg[e] + plb[e];
            hn[e] = sigmoid_ap(ov[e]) * tanh_ap(lnc);
        }
    }
    *(float4*)&h_next[(size_t)b * HID + j4] = *(float4*)hn;
}

// ---------------------------------------------------------------------------
extern "C" void kernel_launch(void* const* d_in, const int* in_sizes, int n_in,
                              void* d_out, int out_size)
{
    const float* x     = (const float*)d_in[0];
    const float* h     = (const float*)d_in[1];
    const float* c     = (const float*)d_in[2];
    const float* W_h   = (const float*)d_in[3];
    const float* b_h   = (const float*)d_in[4];
    const float* W_x   = (const float*)d_in[5];
    const float* ln_g  = (const float*)d_in[6];
    const float* ln_b  = (const float*)d_in[7];
    const float* lnc_g = (const float*)d_in[8];
    const float* lnc_b = (const float*)d_in[9];

    float* out    = (float*)d_out;
    float* h_next = out;
    float* c_next = out + (size_t)BATCH * HID;

    prepass_kernel<<<CVT_BLOCKS + 2 * PACK_BLOCKS_PER_W, 256>>>(h, x, W_h, W_x);

    cudaFuncSetAttribute(gemm_fp16_kernel,
                         cudaFuncAttributeMaxDynamicSharedMemorySize, GEMM_SMEM);
    dim3 grid(NOUT / BN, BATCH / BM);
    gemm_fp16_kernel<<<grid, 256, GEMM_SMEM>>>(b_h);

    ln_lstm_kernel<<<BATCH, 256>>>(c, ln_g, ln_b, lnc_g, lnc_b, h_next, c_next);
}